// round 15
// baseline (speedup 1.0000x reference)
#include <cuda_runtime.h>
#include <cuda_fp16.h>
#include <stdint.h>

#define NLAYER 15
#define NSLOT  6               // ring of 32KB weight slots (layer chunks)

// fp16 fragment-ordered weights: per layer 32KB.
// entry e = kt*8 + nt2: uint4 per lane = (b0 nt 2nt2, b1 nt 2nt2, b0 nt 2nt2+1, b1 nt 2nt2+1)
__device__ __align__(128) unsigned char g_wimg[NLAYER * 32768];

// ---------------- smem layout ----------------
#define SO_FULL   0                    // 6 mbarriers x 8B
#define SO_FILLED 48                   // monotonic chunk-complete counter
#define SO_CNT    64                   // 16 uint32 monotonic chunk counters
#define SO_W1     256                  // 256 floats
#define SO_B1     1280                 // 128 floats
#define SO_W17    1792                 // 128 floats
#define SO_BIAS   2304                 // 15*128 floats
#define SO_WBUF   10240                // 1024-aligned; 6 x 32768 ring
#define SMEM_TOTAL (10240 + NSLOT*32768)   // 206848 B

// ---------------- helpers ----------------
__device__ __forceinline__ uint32_t smem_u32(const void* p) {
    uint32_t a;
    asm("{ .reg .u64 t; cvta.to.shared.u64 t, %1; cvt.u32.u64 %0, t; }" : "=r"(a) : "l"(p));
    return a;
}
__device__ __forceinline__ void mbar_init(uint32_t mbar, uint32_t cnt) {
    asm volatile("mbarrier.init.shared.b64 [%0], %1;" :: "r"(mbar), "r"(cnt) : "memory");
}
__device__ __forceinline__ void mbar_expect_tx(uint32_t mbar, uint32_t bytes) {
    asm volatile("mbarrier.arrive.expect_tx.shared.b64 _, [%0], %1;" :: "r"(mbar), "r"(bytes) : "memory");
}
__device__ __forceinline__ void mbar_wait(uint32_t mbar, uint32_t parity) {
    asm volatile(
        "{\n\t.reg .pred P;\n\t"
        "WL_%=:\n\t"
        "mbarrier.try_wait.parity.acquire.cta.shared::cta.b64 P, [%0], %1, 0x989680;\n\t"
        "@P bra WD_%=;\n\t"
        "bra.uni WL_%=;\n\t"
        "WD_%=:\n\t}"
        :: "r"(mbar), "r"(parity) : "memory");
}
__device__ __forceinline__ void bulk_g2s(uint32_t dst, const void* src, uint32_t bytes, uint32_t mbar) {
    asm volatile("cp.async.bulk.shared::cta.global.mbarrier::complete_tx::bytes [%0], [%1], %2, [%3];"
                 :: "r"(dst), "l"(src), "r"(bytes), "r"(mbar) : "memory");
}
__device__ __forceinline__ uint32_t atom_inc_acqrel(uint32_t addr) {
    uint32_t old;
    asm volatile("atom.acq_rel.cta.shared::cta.add.u32 %0, [%1], 1;"
                 : "=r"(old) : "r"(addr) : "memory");
    return old;
}
__device__ __forceinline__ uint32_t ld_acq(uint32_t addr) {
    uint32_t v;
    asm volatile("ld.acquire.cta.shared.u32 %0, [%1];" : "=r"(v) : "r"(addr) : "memory");
    return v;
}
__device__ __forceinline__ void red_max_rel(uint32_t addr, uint32_t v) {
    asm volatile("red.release.cta.shared.max.u32 [%0], %1;" :: "r"(addr), "r"(v) : "memory");
}
__device__ __forceinline__ uint4 lds128(uint32_t addr) {
    uint4 v;
    asm volatile("ld.shared.v4.b32 {%0,%1,%2,%3}, [%4];"
                 : "=r"(v.x), "=r"(v.y), "=r"(v.z), "=r"(v.w) : "r"(addr));
    return v;
}
__device__ __forceinline__ void mma16816(float* d, const uint32_t* a, uint32_t b0, uint32_t b1) {
    asm volatile(
        "mma.sync.aligned.m16n8k16.row.col.f32.f16.f16.f32 "
        "{%0,%1,%2,%3}, {%4,%5,%6,%7}, {%8,%9}, {%0,%1,%2,%3};"
        : "+f"(d[0]), "+f"(d[1]), "+f"(d[2]), "+f"(d[3])
        : "r"(a[0]), "r"(a[1]), "r"(a[2]), "r"(a[3]), "r"(b0), "r"(b1));
}
__device__ __forceinline__ uint32_t packh2(float a, float b) {
    __half2 h = __float22half2_rn(make_float2(a, b));
    return *reinterpret_cast<uint32_t*>(&h);
}
__device__ __forceinline__ uint32_t packrelu2(float a, float b) {
    __half2 h = __float22half2_rn(make_float2(a, b));
    h = __hmax2(h, __float2half2_rn(0.f));
    return *reinterpret_cast<uint32_t*>(&h);
}

// ---------------- prep: weights -> fp16 per-lane fragment layout ----------------
__global__ void prep_weights(const float* __restrict__ Ws) {
    int idx = blockIdx.x * blockDim.x + threadIdx.x;
    if (idx >= NLAYER * 64 * 32) return;
    int lane  = idx & 31;
    int e     = (idx >> 5) & 63;   // kt*8 + nt2
    int layer = idx >> 11;
    int kt  = e >> 3;
    int nt2 = e & 7;
    int tig = lane & 3;
    int g   = lane >> 2;
    int k0 = kt * 16 + tig * 2;
    const float* W = Ws + layer * 16384;

    auto pk = [&](int k, int n) -> uint32_t {
        return packh2(W[k * 128 + n], W[(k + 1) * 128 + n]);
    };
    int n0 = nt2 * 16 + g;
    uint4 r;
    r.x = pk(k0,     n0);
    r.y = pk(k0 + 8, n0);
    r.z = pk(k0,     n0 + 8);
    r.w = pk(k0 + 8, n0 + 8);
    *reinterpret_cast<uint4*>(&g_wimg[(size_t)layer * 32768u + (size_t)e * 512u
                                      + (size_t)lane * 16u]) = r;
}

// One mid layer for a 32-row warp tile: A0/A1 -> B0/B1 (identical to R13 body).
__device__ __forceinline__ void mlp_step(
    uint32_t wb, const float* bi,
    uint32_t (&A0)[8][4], uint32_t (&A1)[8][4],
    uint32_t (&B0)[8][4], uint32_t (&B1)[8][4])
{
    uint4 w = lds128(wb);                                             // nt2=0, kt=0
    float2 nb0 = *reinterpret_cast<const float2*>(bi);
    float2 nb1 = *reinterpret_cast<const float2*>(bi + 8);
#pragma unroll
    for (int nt2 = 0; nt2 < 8; nt2++) {
        float D[4][4];
        D[0][0] = nb0.x; D[0][1] = nb0.y; D[0][2] = nb0.x; D[0][3] = nb0.y;
        D[1][0] = nb1.x; D[1][1] = nb1.y; D[1][2] = nb1.x; D[1][3] = nb1.y;
        D[2][0] = nb0.x; D[2][1] = nb0.y; D[2][2] = nb0.x; D[2][3] = nb0.y;
        D[3][0] = nb1.x; D[3][1] = nb1.y; D[3][2] = nb1.x; D[3][3] = nb1.y;
        if (nt2 < 7) {
            nb0 = *reinterpret_cast<const float2*>(bi + (2 * nt2 + 2) * 8);
            nb1 = *reinterpret_cast<const float2*>(bi + (2 * nt2 + 3) * 8);
        }
#pragma unroll
        for (int kt = 0; kt < 8; kt++) {
            uint32_t naddr = (kt < 7) ? (uint32_t)(((kt + 1) * 8 + nt2) * 512)
                                      : (uint32_t)(((nt2 + 1) & 7) * 512);
            uint4 wn = lds128(wb + naddr);
            mma16816(D[0], A0[kt], w.x, w.y);
            mma16816(D[1], A0[kt], w.z, w.w);
            mma16816(D[2], A1[kt], w.x, w.y);
            mma16816(D[3], A1[kt], w.z, w.w);
            w = wn;
        }
        B0[nt2][0] = packrelu2(D[0][0], D[0][1]);
        B0[nt2][1] = packrelu2(D[0][2], D[0][3]);
        B0[nt2][2] = packrelu2(D[1][0], D[1][1]);
        B0[nt2][3] = packrelu2(D[1][2], D[1][3]);
        B1[nt2][0] = packrelu2(D[2][0], D[2][1]);
        B1[nt2][1] = packrelu2(D[2][2], D[2][3]);
        B1[nt2][2] = packrelu2(D[3][0], D[3][1]);
        B1[nt2][3] = packrelu2(D[3][2], D[3][3]);
    }
}

// Final hidden layer fused with fc17: returns 4 partial dots.
__device__ __forceinline__ float4 mlp_last(
    uint32_t wb, const float* bi, const float* w7,
    uint32_t (&A0)[8][4], uint32_t (&A1)[8][4])
{
    float s0 = 0.f, s1 = 0.f, s2 = 0.f, s3 = 0.f;
    uint4 w = lds128(wb);
    float2 nb0 = *reinterpret_cast<const float2*>(bi);
    float2 nb1 = *reinterpret_cast<const float2*>(bi + 8);
#pragma unroll
    for (int nt2 = 0; nt2 < 8; nt2++) {
        float D[4][4];
        D[0][0] = nb0.x; D[0][1] = nb0.y; D[0][2] = nb0.x; D[0][3] = nb0.y;
        D[1][0] = nb1.x; D[1][1] = nb1.y; D[1][2] = nb1.x; D[1][3] = nb1.y;
        D[2][0] = nb0.x; D[2][1] = nb0.y; D[2][2] = nb0.x; D[2][3] = nb0.y;
        D[3][0] = nb1.x; D[3][1] = nb1.y; D[3][2] = nb1.x; D[3][3] = nb1.y;
        if (nt2 < 7) {
            nb0 = *reinterpret_cast<const float2*>(bi + (2 * nt2 + 2) * 8);
            nb1 = *reinterpret_cast<const float2*>(bi + (2 * nt2 + 3) * 8);
        }
#pragma unroll
        for (int kt = 0; kt < 8; kt++) {
            uint32_t naddr = (kt < 7) ? (uint32_t)(((kt + 1) * 8 + nt2) * 512)
                                      : (uint32_t)(((nt2 + 1) & 7) * 512);
            uint4 wn = lds128(wb + naddr);
            mma16816(D[0], A0[kt], w.x, w.y);
            mma16816(D[1], A0[kt], w.z, w.w);
            mma16816(D[2], A1[kt], w.x, w.y);
            mma16816(D[3], A1[kt], w.z, w.w);
            w = wn;
        }
        float2 wa = *reinterpret_cast<const float2*>(w7 + (2 * nt2) * 8);
        float2 wc = *reinterpret_cast<const float2*>(w7 + (2 * nt2 + 1) * 8);
        s0 = fmaf(fmaxf(D[0][0], 0.f), wa.x, fmaf(fmaxf(D[0][1], 0.f), wa.y, s0));
        s1 = fmaf(fmaxf(D[0][2], 0.f), wa.x, fmaf(fmaxf(D[0][3], 0.f), wa.y, s1));
        s0 = fmaf(fmaxf(D[1][0], 0.f), wc.x, fmaf(fmaxf(D[1][1], 0.f), wc.y, s0));
        s1 = fmaf(fmaxf(D[1][2], 0.f), wc.x, fmaf(fmaxf(D[1][3], 0.f), wc.y, s1));
        s2 = fmaf(fmaxf(D[2][0], 0.f), wa.x, fmaf(fmaxf(D[2][1], 0.f), wa.y, s2));
        s3 = fmaf(fmaxf(D[2][2], 0.f), wa.x, fmaf(fmaxf(D[2][3], 0.f), wa.y, s3));
        s2 = fmaf(fmaxf(D[3][0], 0.f), wc.x, fmaf(fmaxf(D[3][1], 0.f), wc.y, s2));
        s3 = fmaf(fmaxf(D[3][2], 0.f), wc.x, fmaf(fmaxf(D[3][3], 0.f), wc.y, s3));
    }
    return make_float4(s0, s1, s2, s3);
}

// ---------------- main fused MLP kernel (persistent CTAs) -------------------
__global__ void __launch_bounds__(256, 1)
mlp_kernel(const float* __restrict__ x, const float* __restrict__ W1,
           const float* __restrict__ b1, const float* __restrict__ bs,
           const float* __restrict__ W17, const float* __restrict__ b17,
           float* __restrict__ out, int ntiles) {
    extern __shared__ __align__(1024) unsigned char smem[];
    uint32_t sb = smem_u32(smem);
    int tid  = threadIdx.x;
    int wid  = tid >> 5;
    int lane = tid & 31;
    int g    = lane >> 2;
    int tig  = lane & 3;

    float* sW1  = reinterpret_cast<float*>(smem + SO_W1);
    float* sB1  = reinterpret_cast<float*>(smem + SO_B1);
    float* sW17 = reinterpret_cast<float*>(smem + SO_W17);
    float* sBias= reinterpret_cast<float*>(smem + SO_BIAS);

    if (tid < NSLOT) mbar_init(sb + SO_FULL + 8u * tid, 1);
    if (tid == 0) *reinterpret_cast<uint32_t*>(smem + SO_FILLED) = 0;
    if (tid < 256) sW1[tid] = W1[tid];
    if (tid < 128) { sB1[tid] = b1[tid]; sW17[tid] = W17[tid]; }
    if (tid < 16) reinterpret_cast<uint32_t*>(smem + SO_CNT)[tid] = 0;
    for (int idx = tid; idx < NLAYER * 128; idx += 256) sBias[idx] = bs[idx];
    __syncthreads();

    int mytiles = (ntiles - blockIdx.x + gridDim.x - 1) / gridDim.x;
    int lastchunk = mytiles * NLAYER;

    if (tid == 0) {
#pragma unroll
        for (int j = 0; j < NSLOT; j++) {
            if (j < lastchunk) {
                mbar_expect_tx(sb + SO_FULL + 8u * j, 32768);
                bulk_g2s(sb + SO_WBUF + 32768u * j, &g_wimg[(size_t)(j % NLAYER) * 32768u],
                         32768, sb + SO_FULL + 8u * j);
            }
        }
    }

    float b17v = b17[0];
    const float* biasBase = sBias + tig * 2;

    if (wid) __nanosleep((unsigned)(wid * 250));

    uint32_t A0[8][4], A1[8][4], B0[8][4], B1[8][4];
    int chunk = 0, slot = 0, phase = 0;

    // cheap-flag wait: ld.acquire of monotonic counter; mbar_wait fallback.
    // First passage of any chunk is via the real mbarrier (flag advances only
    // through genuine passes); release/acquire carries TMA-write visibility.
    auto slot_wait = [&]() {
        uint32_t f = ld_acq(sb + SO_FILLED);
        if ((int)f <= chunk) {
            mbar_wait(sb + SO_FULL + 8u * (uint32_t)slot, (uint32_t)phase);
            if (lane == 0) red_max_rel(sb + SO_FILLED, (uint32_t)(chunk + 1));
        }
    };

    auto ring_advance = [&]() {
        if (lane == 0) {
            uint32_t old = atom_inc_acqrel(sb + SO_CNT + 4u * (uint32_t)(chunk & 15));
            if (old == (uint32_t)((chunk >> 4) * 8 + 7) && chunk + NSLOT < lastchunk) {
                asm volatile("fence.proxy.async.shared::cta;" ::: "memory");
                uint32_t fb = sb + SO_FULL + 8u * (uint32_t)slot;
                mbar_expect_tx(fb, 32768);
                bulk_g2s(sb + SO_WBUF + (uint32_t)slot * 32768u,
                         &g_wimg[(size_t)((chunk + NSLOT) % NLAYER) * 32768u], 32768, fb);
            }
        }
        chunk++;
        if (++slot == NSLOT) { slot = 0; phase ^= 1; }
    };

    // preload first tile's inputs
    size_t p0 = (size_t)blockIdx.x * 256 + (size_t)(wid * 32 + g);
    float2 xa = reinterpret_cast<const float2*>(x)[p0];
    float2 xb = reinterpret_cast<const float2*>(x)[p0 + 8];
    float2 xc = reinterpret_cast<const float2*>(x)[p0 + 16];
    float2 xd = reinterpret_cast<const float2*>(x)[p0 + 24];

    for (int tile = blockIdx.x; tile < ntiles; tile += gridDim.x) {
        // ---- fc1: 32 rows per warp -> two m16 fragment sets (from prefetched x) ----
#pragma unroll
        for (int kt = 0; kt < 8; kt++) {
            int c = kt * 16 + tig * 2;
#pragma unroll
            for (int q = 0; q < 2; q++) {
                int cc = c + q * 8;
                float w0 = sW1[cc],     w0y = sW1[128 + cc],     bb0 = sB1[cc];
                float w1 = sW1[cc + 1], w1y = sW1[128 + cc + 1], bb1 = sB1[cc + 1];
                float va0 = fmaf(xa.x, w0, fmaf(xa.y, w0y, bb0));
                float va1 = fmaf(xa.x, w1, fmaf(xa.y, w1y, bb1));
                float vb0 = fmaf(xb.x, w0, fmaf(xb.y, w0y, bb0));
                float vb1 = fmaf(xb.x, w1, fmaf(xb.y, w1y, bb1));
                float vc0 = fmaf(xc.x, w0, fmaf(xc.y, w0y, bb0));
                float vc1 = fmaf(xc.x, w1, fmaf(xc.y, w1y, bb1));
                float vd0 = fmaf(xd.x, w0, fmaf(xd.y, w0y, bb0));
                float vd1 = fmaf(xd.x, w1, fmaf(xd.y, w1y, bb1));
                A0[kt][2 * q]     = packrelu2(va0, va1);
                A0[kt][2 * q + 1] = packrelu2(vb0, vb1);
                A1[kt][2 * q]     = packrelu2(vc0, vc1);
                A1[kt][2 * q + 1] = packrelu2(vd0, vd1);
            }
        }

        // 7 layer pairs with register ping-pong A<->B
#pragma unroll 1
        for (int ii = 0; ii < 7; ii++) {
            {
                slot_wait();
                uint32_t wb = sb + SO_WBUF + (uint32_t)slot * 32768u + (uint32_t)lane * 16u;
                mlp_step(wb, biasBase + (2 * ii) * 128, A0, A1, B0, B1);
                ring_advance();
            }
            {
                slot_wait();
                uint32_t wb = sb + SO_WBUF + (uint32_t)slot * 32768u + (uint32_t)lane * 16u;
                mlp_step(wb, biasBase + (2 * ii + 1) * 128, B0, B1, A0, A1);
                ring_advance();
            }
        }

        {   // layer 14 + fc17 (prefetch next tile's x first: LDG hidden under MMAs)
            slot_wait();
            int ntile = tile + gridDim.x;
            if (ntile < ntiles) {
                size_t np0 = (size_t)ntile * 256 + (size_t)(wid * 32 + g);
                xa = reinterpret_cast<const float2*>(x)[np0];
                xb = reinterpret_cast<const float2*>(x)[np0 + 8];
                xc = reinterpret_cast<const float2*>(x)[np0 + 16];
                xd = reinterpret_cast<const float2*>(x)[np0 + 24];
            }
            uint32_t wb = sb + SO_WBUF + (uint32_t)slot * 32768u + (uint32_t)lane * 16u;
            float4 s = mlp_last(wb, biasBase + (NLAYER - 1) * 128, sW17 + tig * 2, A0, A1);
            ring_advance();
            float s0 = s.x, s1 = s.y, s2 = s.z, s3 = s.w;
            s0 += __shfl_xor_sync(0xFFFFFFFFu, s0, 1);
            s0 += __shfl_xor_sync(0xFFFFFFFFu, s0, 2);
            s1 += __shfl_xor_sync(0xFFFFFFFFu, s1, 1);
            s1 += __shfl_xor_sync(0xFFFFFFFFu, s1, 2);
            s2 += __shfl_xor_sync(0xFFFFFFFFu, s2, 1);
            s2 += __shfl_xor_sync(0xFFFFFFFFu, s2, 2);
            s3 += __shfl_xor_sync(0xFFFFFFFFu, s3, 1);
            s3 += __shfl_xor_sync(0xFFFFFFFFu, s3, 2);
            if (tig == 0) {
                out[p0]      = s0 + b17v;
                out[p0 + 8]  = s1 + b17v;
                out[p0 + 16] = s2 + b17v;
                out[p0 + 24] = s3 + b17v;
            }
            p0 = (size_t)ntile * 256 + (size_t)(wid * 32 + g);
        }
    }
}

// ---------------- launch ----------------
extern "C" void kernel_launch(void* const* d_in, const int* in_sizes, int n_in,
                              void* d_out, int out_size) {
    const float* x   = (const float*)d_in[0];
    const float* W1  = (const float*)d_in[1];
    const float* b1  = (const float*)d_in[2];
    const float* Ws  = (const float*)d_in[3];
    const float* bs  = (const float*)d_in[4];
    const float* W17 = (const float*)d_in[5];
    const float* b17 = (const float*)d_in[6];
    float* out = (float*)d_out;

    cudaFuncSetAttribute(mlp_kernel, cudaFuncAttributeMaxDynamicSharedMemorySize, SMEM_TOTAL);

    int npts = in_sizes[0] / 2;
    int ntiles = npts / 256;

    static int nsm = 0;
    if (nsm == 0) {
        cudaDeviceGetAttribute(&nsm, cudaDevAttrMultiProcessorCount, 0);
        if (nsm <= 0) nsm = 148;
    }
    int nblk = nsm < ntiles ? nsm : ntiles;

    prep_weights<<<(NLAYER * 64 * 32 + 255) / 256, 256>>>(Ws);
    mlp_kernel<<<nblk, 256, SMEM_TOTAL>>>(x, W1, b1, bs, W17, b17, out, ntiles);
}

// round 16
// speedup vs baseline: 1.0464x; 1.0464x over previous
#include <cuda_runtime.h>
#include <cuda_fp16.h>
#include <stdint.h>

#define NLAYER 15
#define NSLOT  6               // ring of 32KB weight slots (layer chunks)

// fp16 fragment-ordered weights: per layer 32KB.
// entry e = kt*8 + nt2: uint4 per lane = (b0 nt 2nt2, b1 nt 2nt2, b0 nt 2nt2+1, b1 nt 2nt2+1)
__device__ __align__(128) unsigned char g_wimg[NLAYER * 32768];

// ---------------- smem layout ----------------
#define SO_FULL   0                    // 6 mbarriers x 8B
#define SO_CNT    64                   // 16 uint32 monotonic chunk counters
#define SO_W1     256                  // 256 floats
#define SO_B1     1280                 // 128 floats
#define SO_W17    1792                 // 128 floats
#define SO_BIAS   2304                 // 15*128 floats
#define SO_WBUF   10240                // 1024-aligned; 6 x 32768 ring
#define SMEM_TOTAL (10240 + NSLOT*32768)   // 206848 B

// ---------------- helpers ----------------
__device__ __forceinline__ uint32_t smem_u32(const void* p) {
    uint32_t a;
    asm("{ .reg .u64 t; cvta.to.shared.u64 t, %1; cvt.u32.u64 %0, t; }" : "=r"(a) : "l"(p));
    return a;
}
__device__ __forceinline__ void mbar_init(uint32_t mbar, uint32_t cnt) {
    asm volatile("mbarrier.init.shared.b64 [%0], %1;" :: "r"(mbar), "r"(cnt) : "memory");
}
__device__ __forceinline__ void mbar_expect_tx(uint32_t mbar, uint32_t bytes) {
    asm volatile("mbarrier.arrive.expect_tx.shared.b64 _, [%0], %1;" :: "r"(mbar), "r"(bytes) : "memory");
}
__device__ __forceinline__ void mbar_wait(uint32_t mbar, uint32_t parity) {
    asm volatile(
        "{\n\t.reg .pred P;\n\t"
        "WL_%=:\n\t"
        "mbarrier.try_wait.parity.acquire.cta.shared::cta.b64 P, [%0], %1, 0x989680;\n\t"
        "@P bra WD_%=;\n\t"
        "bra.uni WL_%=;\n\t"
        "WD_%=:\n\t}"
        :: "r"(mbar), "r"(parity) : "memory");
}
__device__ __forceinline__ void bulk_g2s(uint32_t dst, const void* src, uint32_t bytes, uint32_t mbar) {
    asm volatile("cp.async.bulk.shared::cta.global.mbarrier::complete_tx::bytes [%0], [%1], %2, [%3];"
                 :: "r"(dst), "l"(src), "r"(bytes), "r"(mbar) : "memory");
}
__device__ __forceinline__ uint32_t atom_inc_acqrel(uint32_t addr) {
    uint32_t old;
    asm volatile("atom.acq_rel.cta.shared::cta.add.u32 %0, [%1], 1;"
                 : "=r"(old) : "r"(addr) : "memory");
    return old;
}
__device__ __forceinline__ uint4 lds128(uint32_t addr) {
    uint4 v;
    asm volatile("ld.shared.v4.b32 {%0,%1,%2,%3}, [%4];"
                 : "=r"(v.x), "=r"(v.y), "=r"(v.z), "=r"(v.w) : "r"(addr));
    return v;
}
__device__ __forceinline__ void mma16816(float* d, const uint32_t* a, uint32_t b0, uint32_t b1) {
    asm volatile(
        "mma.sync.aligned.m16n8k16.row.col.f32.f16.f16.f32 "
        "{%0,%1,%2,%3}, {%4,%5,%6,%7}, {%8,%9}, {%0,%1,%2,%3};"
        : "+f"(d[0]), "+f"(d[1]), "+f"(d[2]), "+f"(d[3])
        : "r"(a[0]), "r"(a[1]), "r"(a[2]), "r"(a[3]), "r"(b0), "r"(b1));
}
__device__ __forceinline__ uint32_t packh2(float a, float b) {
    __half2 h = __float22half2_rn(make_float2(a, b));
    return *reinterpret_cast<uint32_t*>(&h);
}
__device__ __forceinline__ uint32_t packrelu2(float a, float b) {
    __half2 h = __float22half2_rn(make_float2(a, b));
    h = __hmax2(h, __float2half2_rn(0.f));
    return *reinterpret_cast<uint32_t*>(&h);
}

// ---------------- prep: weights -> fp16 per-lane fragment layout ----------------
__global__ void prep_weights(const float* __restrict__ Ws) {
    int idx = blockIdx.x * blockDim.x + threadIdx.x;
    if (idx >= NLAYER * 64 * 32) return;
    int lane  = idx & 31;
    int e     = (idx >> 5) & 63;   // kt*8 + nt2
    int layer = idx >> 11;
    int kt  = e >> 3;
    int nt2 = e & 7;
    int tig = lane & 3;
    int g   = lane >> 2;
    int k0 = kt * 16 + tig * 2;
    const float* W = Ws + layer * 16384;

    auto pk = [&](int k, int n) -> uint32_t {
        return packh2(W[k * 128 + n], W[(k + 1) * 128 + n]);
    };
    int n0 = nt2 * 16 + g;
    uint4 r;
    r.x = pk(k0,     n0);
    r.y = pk(k0 + 8, n0);
    r.z = pk(k0,     n0 + 8);
    r.w = pk(k0 + 8, n0 + 8);
    *reinterpret_cast<uint4*>(&g_wimg[(size_t)layer * 32768u + (size_t)e * 512u
                                      + (size_t)lane * 16u]) = r;
}

// One mid layer for a 32-row warp tile: A0/A1 -> B0/B1.
// LDS double-buffer pipelined ACROSS nt2-chunk seams: the kt==7 slot preloads
// chunk nt2+1's kt=0 fragment; next chunk's bias is prefetched mid-chunk.
__device__ __forceinline__ void mlp_step(
    uint32_t wb, const float* bi,
    uint32_t (&A0)[8][4], uint32_t (&A1)[8][4],
    uint32_t (&B0)[8][4], uint32_t (&B1)[8][4])
{
    uint4 w = lds128(wb);                                             // nt2=0, kt=0
    float2 nb0 = *reinterpret_cast<const float2*>(bi);
    float2 nb1 = *reinterpret_cast<const float2*>(bi + 8);
#pragma unroll
    for (int nt2 = 0; nt2 < 8; nt2++) {
        float D[4][4];
        D[0][0] = nb0.x; D[0][1] = nb0.y; D[0][2] = nb0.x; D[0][3] = nb0.y;
        D[1][0] = nb1.x; D[1][1] = nb1.y; D[1][2] = nb1.x; D[1][3] = nb1.y;
        D[2][0] = nb0.x; D[2][1] = nb0.y; D[2][2] = nb0.x; D[2][3] = nb0.y;
        D[3][0] = nb1.x; D[3][1] = nb1.y; D[3][2] = nb1.x; D[3][3] = nb1.y;
        if (nt2 < 7) {
            nb0 = *reinterpret_cast<const float2*>(bi + (2 * nt2 + 2) * 8);
            nb1 = *reinterpret_cast<const float2*>(bi + (2 * nt2 + 3) * 8);
        }
#pragma unroll
        for (int kt = 0; kt < 8; kt++) {
            // next fragment: same chunk kt+1, or next chunk's kt=0 (wrap at end, harmless)
            uint32_t naddr = (kt < 7) ? (uint32_t)(((kt + 1) * 8 + nt2) * 512)
                                      : (uint32_t)(((nt2 + 1) & 7) * 512);
            uint4 wn = lds128(wb + naddr);
            mma16816(D[0], A0[kt], w.x, w.y);
            mma16816(D[1], A0[kt], w.z, w.w);
            mma16816(D[2], A1[kt], w.x, w.y);
            mma16816(D[3], A1[kt], w.z, w.w);
            w = wn;
        }
        B0[nt2][0] = packrelu2(D[0][0], D[0][1]);
        B0[nt2][1] = packrelu2(D[0][2], D[0][3]);
        B0[nt2][2] = packrelu2(D[1][0], D[1][1]);
        B0[nt2][3] = packrelu2(D[1][2], D[1][3]);
        B1[nt2][0] = packrelu2(D[2][0], D[2][1]);
        B1[nt2][1] = packrelu2(D[2][2], D[2][3]);
        B1[nt2][2] = packrelu2(D[3][0], D[3][1]);
        B1[nt2][3] = packrelu2(D[3][2], D[3][3]);
    }
}

// Final hidden layer fused with fc17: returns 4 partial dots.
__device__ __forceinline__ float4 mlp_last(
    uint32_t wb, const float* bi, const float* w7,
    uint32_t (&A0)[8][4], uint32_t (&A1)[8][4])
{
    float s0 = 0.f, s1 = 0.f, s2 = 0.f, s3 = 0.f;
    uint4 w = lds128(wb);
    float2 nb0 = *reinterpret_cast<const float2*>(bi);
    float2 nb1 = *reinterpret_cast<const float2*>(bi + 8);
#pragma unroll
    for (int nt2 = 0; nt2 < 8; nt2++) {
        float D[4][4];
        D[0][0] = nb0.x; D[0][1] = nb0.y; D[0][2] = nb0.x; D[0][3] = nb0.y;
        D[1][0] = nb1.x; D[1][1] = nb1.y; D[1][2] = nb1.x; D[1][3] = nb1.y;
        D[2][0] = nb0.x; D[2][1] = nb0.y; D[2][2] = nb0.x; D[2][3] = nb0.y;
        D[3][0] = nb1.x; D[3][1] = nb1.y; D[3][2] = nb1.x; D[3][3] = nb1.y;
        if (nt2 < 7) {
            nb0 = *reinterpret_cast<const float2*>(bi + (2 * nt2 + 2) * 8);
            nb1 = *reinterpret_cast<const float2*>(bi + (2 * nt2 + 3) * 8);
        }
#pragma unroll
        for (int kt = 0; kt < 8; kt++) {
            uint32_t naddr = (kt < 7) ? (uint32_t)(((kt + 1) * 8 + nt2) * 512)
                                      : (uint32_t)(((nt2 + 1) & 7) * 512);
            uint4 wn = lds128(wb + naddr);
            mma16816(D[0], A0[kt], w.x, w.y);
            mma16816(D[1], A0[kt], w.z, w.w);
            mma16816(D[2], A1[kt], w.x, w.y);
            mma16816(D[3], A1[kt], w.z, w.w);
            w = wn;
        }
        float2 wa = *reinterpret_cast<const float2*>(w7 + (2 * nt2) * 8);
        float2 wc = *reinterpret_cast<const float2*>(w7 + (2 * nt2 + 1) * 8);
        s0 = fmaf(fmaxf(D[0][0], 0.f), wa.x, fmaf(fmaxf(D[0][1], 0.f), wa.y, s0));
        s1 = fmaf(fmaxf(D[0][2], 0.f), wa.x, fmaf(fmaxf(D[0][3], 0.f), wa.y, s1));
        s0 = fmaf(fmaxf(D[1][0], 0.f), wc.x, fmaf(fmaxf(D[1][1], 0.f), wc.y, s0));
        s1 = fmaf(fmaxf(D[1][2], 0.f), wc.x, fmaf(fmaxf(D[1][3], 0.f), wc.y, s1));
        s2 = fmaf(fmaxf(D[2][0], 0.f), wa.x, fmaf(fmaxf(D[2][1], 0.f), wa.y, s2));
        s3 = fmaf(fmaxf(D[2][2], 0.f), wa.x, fmaf(fmaxf(D[2][3], 0.f), wa.y, s3));
        s2 = fmaf(fmaxf(D[3][0], 0.f), wc.x, fmaf(fmaxf(D[3][1], 0.f), wc.y, s2));
        s3 = fmaf(fmaxf(D[3][2], 0.f), wc.x, fmaf(fmaxf(D[3][3], 0.f), wc.y, s3));
    }
    return make_float4(s0, s1, s2, s3);
}

// ---------------- main fused MLP kernel (persistent CTAs) -------------------
__global__ void __launch_bounds__(256, 1)
mlp_kernel(const float* __restrict__ x, const float* __restrict__ W1,
           const float* __restrict__ b1, const float* __restrict__ bs,
           const float* __restrict__ W17, const float* __restrict__ b17,
           float* __restrict__ out, int ntiles) {
    extern __shared__ __align__(1024) unsigned char smem[];
    uint32_t sb = smem_u32(smem);
    int tid  = threadIdx.x;
    int wid  = tid >> 5;
    int lane = tid & 31;
    int g    = lane >> 2;
    int tig  = lane & 3;

    float* sW1  = reinterpret_cast<float*>(smem + SO_W1);
    float* sB1  = reinterpret_cast<float*>(smem + SO_B1);
    float* sW17 = reinterpret_cast<float*>(smem + SO_W17);
    float* sBias= reinterpret_cast<float*>(smem + SO_BIAS);

    if (tid < NSLOT) mbar_init(sb + SO_FULL + 8u * tid, 1);
    if (tid < 256) sW1[tid] = W1[tid];
    if (tid < 128) { sB1[tid] = b1[tid]; sW17[tid] = W17[tid]; }
    if (tid < 16) reinterpret_cast<uint32_t*>(smem + SO_CNT)[tid] = 0;
    for (int idx = tid; idx < NLAYER * 128; idx += 256) sBias[idx] = bs[idx];
    __syncthreads();

    int mytiles = (ntiles - blockIdx.x + gridDim.x - 1) / gridDim.x;
    int lastchunk = mytiles * NLAYER;

    if (tid == 0) {
#pragma unroll
        for (int j = 0; j < NSLOT; j++) {
            if (j < lastchunk) {
                mbar_expect_tx(sb + SO_FULL + 8u * j, 32768);
                bulk_g2s(sb + SO_WBUF + 32768u * j, &g_wimg[(size_t)(j % NLAYER) * 32768u],
                         32768, sb + SO_FULL + 8u * j);
            }
        }
    }

    float b17v = b17[0];
    const float* biasBase = sBias + tig * 2;

    if (wid) __nanosleep((unsigned)(wid * 250));

    uint32_t A0[8][4], A1[8][4], B0[8][4], B1[8][4];
    int chunk = 0, slot = 0, phase = 0;

    auto ring_advance = [&]() {
        if (lane == 0) {
            uint32_t old = atom_inc_acqrel(sb + SO_CNT + 4u * (uint32_t)(chunk & 15));
            if (old == (uint32_t)((chunk >> 4) * 8 + 7) && chunk + NSLOT < lastchunk) {
                asm volatile("fence.proxy.async.shared::cta;" ::: "memory");
                uint32_t fb = sb + SO_FULL + 8u * (uint32_t)slot;
                mbar_expect_tx(fb, 32768);
                bulk_g2s(sb + SO_WBUF + (uint32_t)slot * 32768u,
                         &g_wimg[(size_t)((chunk + NSLOT) % NLAYER) * 32768u], 32768, fb);
            }
        }
        chunk++;
        if (++slot == NSLOT) { slot = 0; phase ^= 1; }
    };

    for (int tile = blockIdx.x; tile < ntiles; tile += gridDim.x) {
        // ---- fc1: 32 rows per warp -> two m16 fragment sets ----
        size_t p0 = (size_t)tile * 256 + (size_t)(wid * 32 + g);
        float2 xa = reinterpret_cast<const float2*>(x)[p0];
        float2 xb = reinterpret_cast<const float2*>(x)[p0 + 8];
        float2 xc = reinterpret_cast<const float2*>(x)[p0 + 16];
        float2 xd = reinterpret_cast<const float2*>(x)[p0 + 24];

#pragma unroll
        for (int kt = 0; kt < 8; kt++) {
            int c = kt * 16 + tig * 2;
#pragma unroll
            for (int q = 0; q < 2; q++) {
                int cc = c + q * 8;
                float w0 = sW1[cc],     w0y = sW1[128 + cc],     bb0 = sB1[cc];
                float w1 = sW1[cc + 1], w1y = sW1[128 + cc + 1], bb1 = sB1[cc + 1];
                float va0 = fmaf(xa.x, w0, fmaf(xa.y, w0y, bb0));
                float va1 = fmaf(xa.x, w1, fmaf(xa.y, w1y, bb1));
                float vb0 = fmaf(xb.x, w0, fmaf(xb.y, w0y, bb0));
                float vb1 = fmaf(xb.x, w1, fmaf(xb.y, w1y, bb1));
                float vc0 = fmaf(xc.x, w0, fmaf(xc.y, w0y, bb0));
                float vc1 = fmaf(xc.x, w1, fmaf(xc.y, w1y, bb1));
                float vd0 = fmaf(xd.x, w0, fmaf(xd.y, w0y, bb0));
                float vd1 = fmaf(xd.x, w1, fmaf(xd.y, w1y, bb1));
                A0[kt][2 * q]     = packrelu2(va0, va1);
                A0[kt][2 * q + 1] = packrelu2(vb0, vb1);
                A1[kt][2 * q]     = packrelu2(vc0, vc1);
                A1[kt][2 * q + 1] = packrelu2(vd0, vd1);
            }
        }

        // 7 layer pairs with register ping-pong A<->B
#pragma unroll 1
        for (int ii = 0; ii < 7; ii++) {
            {
                mbar_wait(sb + SO_FULL + 8u * (uint32_t)slot, (uint32_t)phase);
                uint32_t wb = sb + SO_WBUF + (uint32_t)slot * 32768u + (uint32_t)lane * 16u;
                mlp_step(wb, biasBase + (2 * ii) * 128, A0, A1, B0, B1);
                ring_advance();
            }
            {
                mbar_wait(sb + SO_FULL + 8u * (uint32_t)slot, (uint32_t)phase);
                uint32_t wb = sb + SO_WBUF + (uint32_t)slot * 32768u + (uint32_t)lane * 16u;
                mlp_step(wb, biasBase + (2 * ii + 1) * 128, B0, B1, A0, A1);
                ring_advance();
            }
        }

        {   // layer 14 + fc17
            mbar_wait(sb + SO_FULL + 8u * (uint32_t)slot, (uint32_t)phase);
            uint32_t wb = sb + SO_WBUF + (uint32_t)slot * 32768u + (uint32_t)lane * 16u;
            float4 s = mlp_last(wb, biasBase + (NLAYER - 1) * 128, sW17 + tig * 2, A0, A1);
            ring_advance();
            float s0 = s.x, s1 = s.y, s2 = s.z, s3 = s.w;
            s0 += __shfl_xor_sync(0xFFFFFFFFu, s0, 1);
            s0 += __shfl_xor_sync(0xFFFFFFFFu, s0, 2);
            s1 += __shfl_xor_sync(0xFFFFFFFFu, s1, 1);
            s1 += __shfl_xor_sync(0xFFFFFFFFu, s1, 2);
            s2 += __shfl_xor_sync(0xFFFFFFFFu, s2, 1);
            s2 += __shfl_xor_sync(0xFFFFFFFFu, s2, 2);
            s3 += __shfl_xor_sync(0xFFFFFFFFu, s3, 1);
            s3 += __shfl_xor_sync(0xFFFFFFFFu, s3, 2);
            if (tig == 0) {
                out[p0]      = s0 + b17v;
                out[p0 + 8]  = s1 + b17v;
                out[p0 + 16] = s2 + b17v;
                out[p0 + 24] = s3 + b17v;
            }
        }
    }
}

// ---------------- launch ----------------
extern "C" void kernel_launch(void* const* d_in, const int* in_sizes, int n_in,
                              void* d_out, int out_size) {
    const float* x   = (const float*)d_in[0];
    const float* W1  = (const float*)d_in[1];
    const float* b1  = (const float*)d_in[2];
    const float* Ws  = (const float*)d_in[3];
    const float* bs  = (const float*)d_in[4];
    const float* W17 = (const float*)d_in[5];
    const float* b17 = (const float*)d_in[6];
    float* out = (float*)d_out;

    cudaFuncSetAttribute(mlp_kernel, cudaFuncAttributeMaxDynamicSharedMemorySize, SMEM_TOTAL);

    int npts = in_sizes[0] / 2;
    int ntiles = npts / 256;

    static int nsm = 0;
    if (nsm == 0) {
        cudaDeviceGetAttribute(&nsm, cudaDevAttrMultiProcessorCount, 0);
        if (nsm <= 0) nsm = 148;
    }
    int nblk = nsm < ntiles ? nsm : ntiles;

    prep_weights<<<(NLAYER * 64 * 32 + 255) / 256, 256>>>(Ws);
    mlp_kernel<<<nblk, 256, SMEM_TOTAL>>>(x, W1, b1, bs, W17, b17, out, ntiles);
}